// round 16
// baseline (speedup 1.0000x reference)
#include <cuda_runtime.h>
#include <math.h>

// Problem constants
#define N_SAMPLES 32768
#define N_FRAMES  128
#define STEP      (N_SAMPLES / N_FRAMES)   // 256
#define N_FREQS   16
#define POS_DIM   (2 * N_FREQS + 1)        // 33
#define MODEL_DIM 128
#define N_ROWS    512                      // B * N_EVENTS = 32 * 16

#define PI_D 3.14159265358979323846

// ---------------------------------------------------------------------------
// COMPILE-TIME positional-encoding table, stored TRANSPOSED: posT[j][f] so
// the per-frame dot (thread = frame f) is fully coalesced. Same double-
// precision recurrence that passed R6-R15 with identical argmaxes.
// ---------------------------------------------------------------------------
struct PosTableT { float v[POS_DIM * N_FRAMES]; };   // [j][f]

constexpr double csin_core(double x) {            // |x| <= pi
    double x2 = x * x, term = x, sum = x;
    for (int k = 1; k <= 25; k++) {
        term *= -x2 / (double)((2 * k) * (2 * k + 1));
        sum += term;
    }
    return sum;
}
constexpr double ccos_core(double x) {            // |x| <= pi
    double x2 = x * x, term = 1.0, sum = 1.0;
    for (int k = 1; k <= 25; k++) {
        term *= -x2 / (double)((2 * k - 1) * (2 * k));
        sum += term;
    }
    return sum;
}
constexpr double csqrt_d(double x) {              // Newton, x > 0
    double g = x > 1.0 ? x : 1.0;
    for (int i = 0; i < 80; i++) g = 0.5 * (g + x / g);
    return g;
}

constexpr PosTableT make_pos_table_T() {
    PosTableT T{};
    for (int f = 0; f < N_FRAMES; f++) {
        double xd = -PI_D + (double)f * (2.0 * PI_D / 127.0);
        float x = (float)xd;

        double s = csin_core((double)x);
        double c = ccos_core((double)x);

        float feat[POS_DIM] = {};
        feat[0] = x;
        for (int i = 0; i < N_FREQS; i++) {
            feat[1 + 2 * i] = (float)s;           // sin(2^i * x)
            feat[2 + 2 * i] = (float)c;           // cos(2^i * x)
            double s2 = 2.0 * s * c;
            double c2 = 1.0 - 2.0 * s * s;
            s = s2; c = c2;
        }
        float nrm = 0.0f;
        for (int j = 0; j < POS_DIM; j++) nrm += feat[j] * feat[j];
        float inv = 1.0f / ((float)csqrt_d((double)nrm) + 1e-8f);
        for (int j = 0; j < POS_DIM; j++) T.v[j * N_FRAMES + f] = feat[j] * inv;
    }
    return T;
}

constexpr PosTableT kPosT = make_pos_table_T();    // compile-time
__device__ const PosTableT g_posT = kPosT;

// Producer/consumer state. g_flag/g_done are SELF-RESETTING: the 8th block
// of each row to finish zeroes them, so every launch (and every graph
// replay) starts from the initial all-zero state. Deterministic output.
__device__ int g_delay[N_ROWS];
__device__ int g_flag[N_ROWS];   // static zero-init
__device__ int g_done[N_ROWS];   // static zero-init

// ---------------------------------------------------------------------------
// Per-row delay computation — R11's proven argmax verbatim (W staged to
// shared coalesced, transposed table dot, identical f32 summation orders,
// k-order / j-order / reduction tree / tie rule -> bit-identical delays).
// Runs with 256 threads; compute subsets are tid<128 / tid<33, barriers are
// block-wide. Writes the result into *s_delay (shared).
// ---------------------------------------------------------------------------
__device__ __forceinline__ void compute_delay(
        int row, int tid,
        const float* __restrict__ tl,
        const float* __restrict__ W,
        const float* __restrict__ b,
        float* s_W, float* s_tl, float* s_p,
        float* s_val, int* s_idx, int* s_delay) {
    if (tid < 128) {
        s_tl[tid] = tl[row * MODEL_DIM + tid];
#pragma unroll
        for (int i = 0; i < POS_DIM; i++)
            s_W[i * MODEL_DIM + tid] = W[i * MODEL_DIM + tid];  // flat copy
    }
    __syncthreads();

    if (tid < POS_DIM) {
        float acc = 0.0f;
#pragma unroll 8
        for (int k = 0; k < MODEL_DIM; k++)
            acc += s_tl[k] * s_W[k * POS_DIM + tid];   // same k-order as always
        s_p[tid] = acc + b[tid];
    }
    __syncthreads();

    if (tid < N_FRAMES) {
        float dot = 0.0f;
#pragma unroll
        for (int j = 0; j < POS_DIM; j++)
            dot += s_p[j] * g_posT.v[j * N_FRAMES + tid];  // coalesced in tid
        s_val[tid] = dot;
        s_idx[tid] = tid;
    }
    __syncthreads();

    // argmax; exact tie -> lower index (matches jnp.argmax)
    for (int s = 64; s > 0; s >>= 1) {
        if (tid < s) {
            float vu = s_val[tid + s];
            int   iu = s_idx[tid + s];
            if (vu > s_val[tid] || (vu == s_val[tid] && iu < s_idx[tid])) {
                s_val[tid] = vu;
                s_idx[tid] = iu;
            }
        }
        __syncthreads();
    }
    if (tid == 0) *s_delay = s_idx[0] * STEP;
    __syncthreads();
}

// ---------------------------------------------------------------------------
// ONE kernel, 4096 blocks x 256 threads (1-D). Block b: row = b>>3,
// chunk = b&7.
//   chunk==0 (feeder): compute row's delay ONCE (512 preludes total, like
//     the split argmax kernel), publish via fence + flag, then stream.
//   chunk>0: bounded spin on the flag (feeder has a lower blockIdx ->
//     dispatched no later; fallback computes the delay locally if the spin
//     budget is exceeded, so deadlock is impossible), then stream.
// Streaming = R11's proven 14.7us config: 4 front-batched independent
// float4 loads per thread, __stcs streaming stores, d % 256 == 0 keeps all
// float4 16B-aligned. Epilogue: 8th finisher per row resets flag+counter.
// ---------------------------------------------------------------------------
#define NLD   4
#define CHUNK (256 * 4 * NLD)   // 4096 samples per block
#define SPIN_LIMIT 2000000

__global__ void __launch_bounds__(256) fused_kernel(
        const float* __restrict__ tl,
        const float* __restrict__ W,
        const float* __restrict__ b,
        const float* __restrict__ stems,
        float* __restrict__ out) {
    const int bid   = blockIdx.x;
    const int row   = bid >> 3;
    const int chunk = bid & 7;
    const int tid   = threadIdx.x;   // 0..255

    __shared__ float s_W[MODEL_DIM * POS_DIM];   // 16.5 KB
    __shared__ float s_tl[MODEL_DIM];
    __shared__ float s_p[POS_DIM];
    __shared__ float s_val[N_FRAMES];
    __shared__ int   s_idx[N_FRAMES];
    __shared__ int   s_delay;
    __shared__ int   s_fallback;

    if (chunk == 0) {
        // ---- feeder: compute + publish ----
        compute_delay(row, tid, tl, W, b, s_W, s_tl, s_p, s_val, s_idx, &s_delay);
        if (tid == 0) {
            g_delay[row] = s_delay;
            __threadfence();                       // delay visible before flag
            atomicExch(&g_flag[row], 1);
        }
    } else {
        // ---- consumer: bounded spin, then read ----
        if (tid == 0) {
            s_fallback = 0;
            volatile int* vf = g_flag + row;
            int it = 0;
            while (vf[0] == 0) {
                if (++it > SPIN_LIMIT) { s_fallback = 1; break; }
                __nanosleep(64);
            }
            if (!s_fallback) {
                __threadfence();                   // acquire delay after flag
                s_delay = g_delay[row];
            }
        }
        __syncthreads();
        if (s_fallback) {
            // deterministic local recompute (same math, no global writes)
            compute_delay(row, tid, tl, W, b, s_W, s_tl, s_p, s_val, s_idx, &s_delay);
        }
    }
    __syncthreads();

    // ---- streaming: out[row,t] = (t >= d) ? stems[row, t-d]/256 : 0 ----
    const int d = s_delay;
    const float SCALE = 1.0f / 256.0f;   // 1/sqrt(2*N_SAMPLES), exact pow2

    const float* src = stems + (size_t)row * N_SAMPLES;
    float* dstf      = out   + (size_t)row * N_SAMPLES;
    const int base   = chunk * CHUNK + tid * 4;

    float4 v[NLD];
#pragma unroll
    for (int i = 0; i < NLD; i++) v[i] = make_float4(0.f, 0.f, 0.f, 0.f);

    // front-batch all independent loads (predicated: t < d loads nothing)
#pragma unroll
    for (int i = 0; i < NLD; i++) {
        int t = base + i * 1024;         // 256 threads * 4 floats
        if (t >= d)
            v[i] = *reinterpret_cast<const float4*>(src + (t - d));
    }

#pragma unroll
    for (int i = 0; i < NLD; i++) {
        v[i].x *= SCALE; v[i].y *= SCALE; v[i].z *= SCALE; v[i].w *= SCALE;
        int t = base + i * 1024;
        __stcs(reinterpret_cast<float4*>(dstf + t), v[i]);   // streaming store
    }

    // ---- epilogue: self-reset for the next launch / graph replay ----
    __syncthreads();
    if (tid == 0) {
        int n = atomicAdd(&g_done[row], 1);
        if (n == 7) {                    // last of the row's 8 blocks
            g_done[row] = 0;
            __threadfence();
            g_flag[row] = 0;
        }
    }
}

// ---------------------------------------------------------------------------
extern "C" void kernel_launch(void* const* d_in, const int* in_sizes, int n_in,
                              void* d_out, int out_size) {
    // metadata order: time_latent, stems, targets (unused), W, b
    const float* tl    = (const float*)d_in[0];
    const float* stems = (const float*)d_in[1];
    const float* W     = (const float*)d_in[3];
    const float* b     = (const float*)d_in[4];
    float* out = (float*)d_out;

    fused_kernel<<<N_ROWS * 8, 256>>>(tl, W, b, stems, out);
}